// round 3
// baseline (speedup 1.0000x reference)
#include <cuda_runtime.h>

#define N_NODES 4096
#define E_EDGES 131072
#define ET (E_EDGES + N_NODES)
#define NHID 3
#define NEG_SLOPE 0.2f

// ---------------- scratch (device globals; no allocations) ----------------
__device__ float g_z[N_NODES * NHID];
__device__ float g_zs[N_NODES];
__device__ float g_zd[N_NODES];
__device__ float g_e[ET];
__device__ unsigned g_m[N_NODES];          // ordered-uint encoded segment max
__device__ float g_S[N_NODES];             // segment sum of w
__device__ float g_acc[N_NODES * NHID];    // segment sum of w*z
__device__ float g_xf[N_NODES];
__device__ unsigned long long g_pack[N_NODES];
__device__ int g_start;
__device__ float g_p12;

// order-preserving float<->uint (total order matches float compare)
__device__ __forceinline__ unsigned f2o(float f) {
    unsigned u = __float_as_uint(f);
    return (u & 0x80000000u) ? ~u : (u | 0x80000000u);
}
__device__ __forceinline__ float o2f(unsigned u) {
    return (u & 0x80000000u) ? __uint_as_float(u & 0x7FFFFFFFu)
                             : __uint_as_float(~u);
}

// ---------------- layer 1 prep ----------------
__global__ void k_prep1(const float* __restrict__ x, const float* __restrict__ W1,
                        const float* __restrict__ as1, const float* __restrict__ ad1) {
    int i = blockIdx.x * blockDim.x + threadIdx.x;
    if (i >= N_NODES) return;
    float cs = 0.f, cd = 0.f;
#pragma unroll
    for (int h = 0; h < NHID; h++) { cs += W1[h] * as1[h]; cd += W1[h] * ad1[h]; }
    float xv = x[i];
#pragma unroll
    for (int h = 0; h < NHID; h++) g_z[i * NHID + h] = xv * W1[h];
    g_zs[i] = xv * cs;
    g_zd[i] = xv * cd;
    g_m[i] = 0u;            // below any encoded finite float; self-loop overwrites
    g_S[i] = 0.f;
#pragma unroll
    for (int h = 0; h < NHID; h++) g_acc[i * NHID + h] = 0.f;
    g_pack[i] = 0ull;
}

// ---------------- edge pass A: e + segment max ----------------
__global__ void k_edge_max(const int* __restrict__ ei) {
    int e = blockIdx.x * blockDim.x + threadIdx.x;
    if (e >= ET) return;
    int s, d;
    if (e < E_EDGES) { s = ei[e]; d = ei[E_EDGES + e]; }
    else             { s = e - E_EDGES; d = s; }          // self loop
    float t = g_zs[s] + g_zd[d];
    float ev = (t >= 0.f) ? t : NEG_SLOPE * t;            // leaky_relu
    g_e[e] = ev;
    atomicMax(&g_m[d], f2o(ev));
}

// ---------------- edge pass B: w = exp(e-m), segment sums ----------------
template <int D>
__global__ void k_edge_acc(const int* __restrict__ ei) {
    int e = blockIdx.x * blockDim.x + threadIdx.x;
    if (e >= ET) return;
    int s, d;
    if (e < E_EDGES) { s = ei[e]; d = ei[E_EDGES + e]; }
    else             { s = e - E_EDGES; d = s; }
    float w = expf(g_e[e] - o2f(g_m[d]));
    atomicAdd(&g_S[d], w);
#pragma unroll
    for (int k = 0; k < D; k++)
        atomicAdd(&g_acc[d * D + k], w * g_z[s * D + k]);
}

// ---------------- finish layer1 (+relu) and prep layer2 ----------------
__global__ void k_fin1(const float* __restrict__ b1, const float* __restrict__ W2,
                       const float* __restrict__ as2, const float* __restrict__ ad2) {
    int i = blockIdx.x * blockDim.x + threadIdx.x;
    if (i >= N_NODES) return;
    float Sv = g_S[i] + 1e-16f;
    float h[NHID];
#pragma unroll
    for (int k = 0; k < NHID; k++)
        h[k] = fmaxf(g_acc[i * NHID + k] / Sv + b1[k], 0.f);
    float zs = 0.f, zd = 0.f;
#pragma unroll
    for (int r = 0; r < NHID; r++) {
        float z = 0.f;
#pragma unroll
        for (int c = 0; c < NHID; c++) z += h[c] * W2[r * NHID + c];
        g_z[i * NHID + r] = z;
        zs += z * as2[r];
        zd += z * ad2[r];
    }
    g_zs[i] = zs; g_zd[i] = zd;
    g_m[i] = 0u; g_S[i] = 0.f;
#pragma unroll
    for (int k = 0; k < NHID; k++) g_acc[i * NHID + k] = 0.f;
}

// ---------------- finish layer2 (+relu) and prep layer3 ----------------
__global__ void k_fin2(const float* __restrict__ b2, const float* __restrict__ W3,
                       const float* __restrict__ as3, const float* __restrict__ ad3) {
    int i = blockIdx.x * blockDim.x + threadIdx.x;
    if (i >= N_NODES) return;
    float Sv = g_S[i] + 1e-16f;
    float z = 0.f;
#pragma unroll
    for (int c = 0; c < NHID; c++) {
        float hc = fmaxf(g_acc[i * NHID + c] / Sv + b2[c], 0.f);
        z += hc * W3[c];
    }
    g_z[i] = z;                 // D=1 layout
    g_zs[i] = z * as3[0];
    g_zd[i] = z * ad3[0];
    g_m[i] = 0u; g_S[i] = 0.f;
#pragma unroll
    for (int k = 0; k < NHID; k++) g_acc[i * NHID + k] = 0.f;
}

// ---------------- softmax + argmax(xf) + p12, single block ----------------
__global__ void k_softmax(const float* __restrict__ b3,
                          const float* __restrict__ phi1, const float* __restrict__ phi2,
                          float* __restrict__ out) {
    __shared__ float sh[N_NODES];   // 16 KB
    __shared__ float red[1024];
    __shared__ int   redi[1024];
    int t = threadIdx.x;
    float bias = b3[0];
    float lmax = -__int_as_float(0x7F800000);   // -inf
    for (int i = t; i < N_NODES; i += 1024) {
        float h3 = g_acc[i] / (g_S[i] + 1e-16f) + bias;
        sh[i] = h3;
        lmax = fmaxf(lmax, h3);
    }
    red[t] = lmax; __syncthreads();
    for (int s = 512; s > 0; s >>= 1) {
        if (t < s) red[t] = fmaxf(red[t], red[t + s]);
        __syncthreads();
    }
    float mx = red[0]; __syncthreads();

    float lsum = 0.f;
    for (int i = t; i < N_NODES; i += 1024) {
        float ex = expf(sh[i] - mx);
        sh[i] = ex;
        lsum += ex;
    }
    red[t] = lsum; __syncthreads();
    for (int s = 512; s > 0; s >>= 1) {
        if (t < s) red[t] += red[t + s];
        __syncthreads();
    }
    float sm = red[0]; __syncthreads();

    // write xf, find argmax (first index on ties)
    float bv = -__int_as_float(0x7F800000);
    int bi = 0x7FFFFFFF;
    for (int i = t; i < N_NODES; i += 1024) {
        float xf = sh[i] / sm;
        g_xf[i] = xf;
        out[i] = xf;
        if (xf > bv) { bv = xf; bi = i; }
    }
    red[t] = bv; redi[t] = bi; __syncthreads();
    for (int s = 512; s > 0; s >>= 1) {
        if (t < s) {
            if (red[t + s] > red[t] ||
                (red[t + s] == red[t] && redi[t + s] < redi[t])) {
                red[t] = red[t + s]; redi[t] = redi[t + s];
            }
        }
        __syncthreads();
    }
    if (t == 0) g_start = redi[0];
    __syncthreads();

    // p12 = dot(phi1, phi2) over 128 dims
    float lp = (t < 128) ? phi1[t] * phi2[t] : 0.f;
    red[t] = lp; __syncthreads();
    for (int s = 512; s > 0; s >>= 1) {
        if (t < s) red[t] += red[t + s];
        __syncthreads();
    }
    if (t == 0) g_p12 = red[0];
}

// ---------------- precompute next[s] via packed atomicMax ----------------
// key high 32 bits: ordered xf[dst]-bits (or complement for p12<0, 0 for p12==0)
// low 32 bits: 0xFFFFFFFF - e  -> among equal keys, smaller edge index wins
__global__ void k_pack(const int* __restrict__ ei) {
    int e = blockIdx.x * blockDim.x + threadIdx.x;
    if (e >= E_EDGES) return;
    float p = g_p12;
    int s = ei[e];
    int d = ei[E_EDGES + e];
    unsigned bits = __float_as_uint(g_xf[d]);   // xf >= 0 -> bits already ordered
    unsigned key = (p > 0.f) ? bits : ((p < 0.f) ? ~bits : 0u);
    unsigned long long pk =
        ((unsigned long long)key << 32) |
        (unsigned long long)(0xFFFFFFFFu - (unsigned)e);
    atomicMax(&g_pack[s], pk);
}

// ---------------- pointer chase with cycle shortcut ----------------
__global__ void k_chase(const int* __restrict__ ei, float* __restrict__ out,
                        int out_size) {
    __shared__ int s_next[N_NODES];
    __shared__ int s_vis[N_NODES];
    int dst0_first = ei[E_EDGES];   // dst0[0]: result for degree-0 nodes
    for (int i = threadIdx.x; i < N_NODES; i += blockDim.x) {
        unsigned long long pk = g_pack[i];
        int nx;
        if (pk == 0ull) nx = dst0_first;
        else {
            unsigned e = 0xFFFFFFFFu - (unsigned)(pk & 0xFFFFFFFFull);
            nx = ei[E_EDGES + e];
        }
        s_next[i] = nx;
        s_vis[i] = -1;
    }
    __syncthreads();
    if (threadIdx.x == 0) {
        int s = g_start;
        int k = 0;
        while (k < N_NODES) {
            int v = s_vis[s];
            if (v >= 0) {                        // cycle found
                int L = k - v;
                int rem = (N_NODES - k) % L;
                for (int t2 = 0; t2 < rem; t2++) s = s_next[s];
                break;
            }
            s_vis[s] = k;
            s = s_next[s];
            k++;
        }
        if (out_size > N_NODES) out[N_NODES] = (float)s;
    }
}

// ---------------- launch ----------------
extern "C" void kernel_launch(void* const* d_in, const int* in_sizes, int n_in,
                              void* d_out, int out_size) {
    const float* x   = (const float*)d_in[0];
    const int*   ei  = (const int*)  d_in[1];
    const float* W1  = (const float*)d_in[2];
    const float* as1 = (const float*)d_in[3];
    const float* ad1 = (const float*)d_in[4];
    const float* b1  = (const float*)d_in[5];
    const float* W2  = (const float*)d_in[6];
    const float* as2 = (const float*)d_in[7];
    const float* ad2 = (const float*)d_in[8];
    const float* b2  = (const float*)d_in[9];
    const float* W3  = (const float*)d_in[10];
    const float* as3 = (const float*)d_in[11];
    const float* ad3 = (const float*)d_in[12];
    const float* b3  = (const float*)d_in[13];
    const float* phi1 = (const float*)d_in[14];
    const float* phi2 = (const float*)d_in[15];
    float* out = (float*)d_out;

    const int TB = 256;
    int gn = (N_NODES + TB - 1) / TB;
    int ge = (ET + TB - 1) / TB;
    int gE = (E_EDGES + TB - 1) / TB;

    k_prep1<<<gn, TB>>>(x, W1, as1, ad1);
    k_edge_max<<<ge, TB>>>(ei);
    k_edge_acc<NHID><<<ge, TB>>>(ei);
    k_fin1<<<gn, TB>>>(b1, W2, as2, ad2);
    k_edge_max<<<ge, TB>>>(ei);
    k_edge_acc<NHID><<<ge, TB>>>(ei);
    k_fin2<<<gn, TB>>>(b2, W3, as3, ad3);
    k_edge_max<<<ge, TB>>>(ei);
    k_edge_acc<1><<<ge, TB>>>(ei);
    k_softmax<<<1, 1024>>>(b3, phi1, phi2, out);
    k_pack<<<gE, TB>>>(ei);
    k_chase<<<1, TB>>>(ei, out, out_size);
}